// round 6
// baseline (speedup 1.0000x reference)
#include <cuda_runtime.h>
#include <cstdint>
#include <math.h>

#define BB   64
#define NN   1024
#define CCH  64
#define KK   16
#define NPTS (BB*NN)

// ---------------- scratch (device globals; no allocation allowed) ----------------
__device__ float g_X1[NPTS*CCH];
__device__ float g_X2[NPTS*CCH];
__device__ float g_X3[NPTS*CCH];
__device__ float g_P [NPTS*CCH];
__device__ float g_V [NPTS*CCH];
__device__ float g_D [(size_t)NPTS*NN];   // 256 MB distance scratch
__device__ int   g_IDX[NPTS*KK];
__device__ float g_SQ[NPTS];

// ---------------- squared norms ----------------
__global__ __launch_bounds__(256) void sq_kernel(const float* __restrict__ X, int Cin){
    int w    = (blockIdx.x*256 + threadIdx.x) >> 5;
    int lane = threadIdx.x & 31;
    if (w >= NPTS) return;
    float s = 0.f;
    for (int k = lane; k < Cin; k += 32){ float v = X[(size_t)w*Cin + k]; s += v*v; }
    #pragma unroll
    for (int off = 16; off; off >>= 1) s += __shfl_down_sync(0xffffffffu, s, off);
    if (lane == 0) g_SQ[w] = s;
}

// ---------------- distance matrix, C=1 (layer 1) ----------------
__global__ __launch_bounds__(256) void dist1_kernel(const float* __restrict__ X){
    int b = blockIdx.y, i = blockIdx.x;
    float xi = X[b*NN + i];
    float si = g_SQ[b*NN + i];
    size_t rb = ((size_t)(b*NN + i))*NN;
    for (int j = threadIdx.x; j < NN; j += 256)
        g_D[rb + j] = si + g_SQ[b*NN + j] - 2.f*xi*X[b*NN + j];
}

// ---------------- distance matrix, C=64 (layers 2,3) ----------------
// 64x64 output tile per block, K=64, 4x4 register blocking, float4 smem reads.
__global__ __launch_bounds__(256) void distC_kernel(const float* __restrict__ X){
    int b  = blockIdx.z;
    int i0 = blockIdx.y << 6, j0 = blockIdx.x << 6;
    __shared__ __align__(16) float AT[64][68];   // [k][i]
    __shared__ __align__(16) float BT[64][68];   // [k][j]
    const float* Xb = X + ((size_t)b*NN)*CCH;
    for (int t = threadIdx.x; t < 4096; t += 256){
        int r = t >> 6, k = t & 63;
        AT[k][r] = Xb[(size_t)(i0 + r)*CCH + k];
        BT[k][r] = Xb[(size_t)(j0 + r)*CCH + k];
    }
    __syncthreads();
    int er = threadIdx.x >> 4, cc = threadIdx.x & 15;
    float acc[4][4] = {};
    #pragma unroll 8
    for (int k = 0; k < 64; k++){
        float4 a = *(const float4*)&AT[k][er << 2];
        float4 w = *(const float4*)&BT[k][cc << 2];
        acc[0][0]+=a.x*w.x; acc[0][1]+=a.x*w.y; acc[0][2]+=a.x*w.z; acc[0][3]+=a.x*w.w;
        acc[1][0]+=a.y*w.x; acc[1][1]+=a.y*w.y; acc[1][2]+=a.y*w.z; acc[1][3]+=a.y*w.w;
        acc[2][0]+=a.z*w.x; acc[2][1]+=a.z*w.y; acc[2][2]+=a.z*w.z; acc[2][3]+=a.z*w.w;
        acc[3][0]+=a.w*w.x; acc[3][1]+=a.w*w.y; acc[3][2]+=a.w*w.z; acc[3][3]+=a.w*w.w;
    }
    float sqj[4];
    #pragma unroll
    for (int c = 0; c < 4; c++) sqj[c] = g_SQ[b*NN + j0 + (cc << 2) + c];
    #pragma unroll
    for (int r = 0; r < 4; r++){
        int i = i0 + (er << 2) + r;
        float si = g_SQ[b*NN + i];
        float4 o;
        o.x = si + sqj[0] - 2.f*acc[r][0];
        o.y = si + sqj[1] - 2.f*acc[r][1];
        o.z = si + sqj[2] - 2.f*acc[r][2];
        o.w = si + sqj[3] - 2.f*acc[r][3];
        *(float4*)&g_D[((size_t)(b*NN + i))*NN + j0 + (cc << 2)] = o;
    }
}

// ---------------- top-K (K=16 smallest, tie -> lower index, matches lax.top_k) ----------------
__global__ __launch_bounds__(256) void topk_kernel(void){
    int w    = (blockIdx.x*256 + threadIdx.x) >> 5;   // global row = b*NN+i
    int lane = threadIdx.x & 31;
    if (w >= NPTS) return;
    const float* __restrict__ row = g_D + (size_t)w*NN;

    float ld[16]; int li[16];
    #pragma unroll
    for (int s = 0; s < 16; s++){ ld[s] = 3.4e38f; li[s] = 0x7fffffff; }

    for (int t = 0; t < 32; t++){
        int j = lane + (t << 5);
        float d = row[j];
        if (d < ld[15] || (d == ld[15] && j < li[15])){
            ld[15] = d; li[15] = j;
            #pragma unroll
            for (int s = 15; s > 0; --s){
                bool sw = (ld[s] < ld[s-1]) || (ld[s] == ld[s-1] && li[s] < li[s-1]);
                if (sw){
                    float tf = ld[s-1]; ld[s-1] = ld[s]; ld[s] = tf;
                    int   ti = li[s-1]; li[s-1] = li[s]; li[s] = ti;
                }
            }
        }
    }
    // merge 32 sorted lists: 16 rounds of warp argmin over heads
    for (int r = 0; r < 16; r++){
        float cd = ld[0]; int cj = li[0];
        #pragma unroll
        for (int off = 16; off; off >>= 1){
            float od = __shfl_down_sync(0xffffffffu, cd, off);
            int   oj = __shfl_down_sync(0xffffffffu, cj, off);
            if (od < cd || (od == cd && oj < cj)){ cd = od; cj = oj; }
        }
        cd = __shfl_sync(0xffffffffu, cd, 0);
        cj = __shfl_sync(0xffffffffu, cj, 0);
        if (lane == 0) g_IDX[w*KK + r] = cj;
        if (li[0] == cj){   // pop winner (j unique per lane)
            #pragma unroll
            for (int s = 0; s < 15; s++){ ld[s] = ld[s+1]; li[s] = li[s+1]; }
            ld[15] = 3.4e38f; li[15] = 0x7fffffff;
        }
    }
}

// ---------------- per-point transforms: P = x@(W1a-W1b)+b1, V = x@W1b ----------------
__global__ __launch_bounds__(256) void pv_kernel(const float* __restrict__ X,
                                                 const float* __restrict__ W1,
                                                 const float* __restrict__ B1, int Cin){
    __shared__ float xs[4][64];
    int base = blockIdx.x << 2;   // 4 points per block
    for (int t = threadIdx.x; t < 4*Cin; t += 256)
        xs[t/Cin][t%Cin] = X[(size_t)(base + t/Cin)*Cin + (t % Cin)];
    __syncthreads();
    int lp = threadIdx.x >> 6, c = threadIdx.x & 63;
    float p = B1[c], v = 0.f;
    for (int k = 0; k < Cin; k++){
        float xk = xs[lp][k];
        float wa = W1[k*64 + c];
        float wb = W1[(Cin + k)*64 + c];
        v = fmaf(xk, wb, v);
        p = fmaf(xk, wa - wb, p);
    }
    g_P[(size_t)(base + lp)*64 + c] = p;
    g_V[(size_t)(base + lp)*64 + c] = v;
}

// ---------------- edge GEMM + max: out[i][c] = max_j (relu(P_i+V_j) @ W2)[c] + b2[c] ----------------
// 4 points/block -> 64 edges x 64 channels tile, K=64, 4x4 register blocking.
__global__ __launch_bounds__(256) void edge_kernel(const float* __restrict__ W2,
                                                   const float* __restrict__ B2,
                                                   float* __restrict__ Xout){
    __shared__ __align__(16) float HT [64][68];   // [k][edge]
    __shared__ __align__(16) float W2s[64][68];   // [k][c]
    __shared__ __align__(16) float red[16][68];
    __shared__ int sj[64];
    int tid  = threadIdx.x;
    int base = blockIdx.x << 2;            // 4 points, same batch (1024-aligned batches)
    int b    = base >> 10;
    const float* Vb = g_V + (((size_t)b) << 10)*64;

    if (tid < 64) sj[tid] = g_IDX[(base + (tid >> 4))*KK + (tid & 15)];
    for (int t = tid; t < 4096; t += 256){
        int k = t >> 6, c = t & 63;
        W2s[k][c] = W2[k*64 + c];
    }
    __syncthreads();

    for (int t = tid; t < 4096; t += 256){
        int e = t >> 6, k = t & 63;
        int p = e >> 4;
        float h = g_P[(size_t)(base + p)*64 + k] + Vb[(size_t)sj[e]*64 + k];
        HT[k][e] = fmaxf(h, 0.f);
    }
    __syncthreads();

    int er = tid >> 4, cc = tid & 15;
    float acc[4][4] = {};
    #pragma unroll 8
    for (int k = 0; k < 64; k++){
        float4 h = *(const float4*)&HT [k][er << 2];
        float4 w = *(const float4*)&W2s[k][cc << 2];
        acc[0][0]+=h.x*w.x; acc[0][1]+=h.x*w.y; acc[0][2]+=h.x*w.z; acc[0][3]+=h.x*w.w;
        acc[1][0]+=h.y*w.x; acc[1][1]+=h.y*w.y; acc[1][2]+=h.y*w.z; acc[1][3]+=h.y*w.w;
        acc[2][0]+=h.z*w.x; acc[2][1]+=h.z*w.y; acc[2][2]+=h.z*w.z; acc[2][3]+=h.z*w.w;
        acc[3][0]+=h.w*w.x; acc[3][1]+=h.w*w.y; acc[3][2]+=h.w*w.z; acc[3][3]+=h.w*w.w;
    }
    // max over this thread's 4 edges (all belong to one point)
    #pragma unroll
    for (int c = 0; c < 4; c++){
        float m = fmaxf(fmaxf(acc[0][c], acc[1][c]), fmaxf(acc[2][c], acc[3][c]));
        red[er][(cc << 2) + c] = m;
    }
    __syncthreads();
    int p = tid >> 6, c = tid & 63;
    float m = red[4*p][c];
    m = fmaxf(m, red[4*p + 1][c]);
    m = fmaxf(m, red[4*p + 2][c]);
    m = fmaxf(m, red[4*p + 3][c]);
    Xout[(size_t)(base + p)*64 + c] = m + B2[c];
}

// ---------------- MLP head + log_softmax ----------------
__global__ __launch_bounds__(128) void head_kernel(const float* __restrict__ mw1, const float* __restrict__ mb1,
                                                   const float* __restrict__ mw2, const float* __restrict__ mb2,
                                                   const float* __restrict__ mw3, const float* __restrict__ mb3,
                                                   const float* __restrict__ mw4, const float* __restrict__ mb4,
                                                   float* __restrict__ out){
    __shared__ float in[192], h1[128], h2[64], h3[32], o2[2];
    int t = threadIdx.x;
    int p0 = blockIdx.x * 16;
    for (int p = p0; p < p0 + 16; p++){
        if (t < 64){
            in[t      ] = g_X1[(size_t)p*64 + t];
            in[t +  64] = g_X2[(size_t)p*64 + t];
            in[t + 128] = g_X3[(size_t)p*64 + t];
        }
        __syncthreads();
        {
            float a = mb1[t];
            #pragma unroll 8
            for (int k = 0; k < 192; k++) a = fmaf(in[k], mw1[k*128 + t], a);
            h1[t] = fmaxf(a, 0.f);
        }
        __syncthreads();
        if (t < 64){
            float a = mb2[t];
            #pragma unroll 8
            for (int k = 0; k < 128; k++) a = fmaf(h1[k], mw2[k*64 + t], a);
            h2[t] = fmaxf(a, 0.f);
        }
        __syncthreads();
        if (t < 32){
            float a = mb3[t];
            #pragma unroll 8
            for (int k = 0; k < 64; k++) a = fmaf(h2[k], mw3[k*32 + t], a);
            h3[t] = fmaxf(a, 0.f);
        }
        __syncthreads();
        if (t < 2){
            float a = mb4[t];
            #pragma unroll
            for (int k = 0; k < 32; k++) a = fmaf(h3[k], mw4[k*2 + t], a);
            o2[t] = a;
        }
        __syncthreads();
        if (t < 2){
            float m   = fmaxf(o2[0], o2[1]);
            float lse = m + logf(expf(o2[0] - m) + expf(o2[1] - m));
            out[(size_t)p*2 + t] = o2[t] - lse;
        }
        __syncthreads();
    }
}

// ---------------- launch ----------------
extern "C" void kernel_launch(void* const* d_in, const int* in_sizes, int n_in,
                              void* d_out, int out_size){
    const float* x    = (const float*)d_in[0];
    const float* c1w1 = (const float*)d_in[1];
    const float* c1b1 = (const float*)d_in[2];
    const float* c1w2 = (const float*)d_in[3];
    const float* c1b2 = (const float*)d_in[4];
    const float* c2w1 = (const float*)d_in[5];
    const float* c2b1 = (const float*)d_in[6];
    const float* c2w2 = (const float*)d_in[7];
    const float* c2b2 = (const float*)d_in[8];
    const float* c3w1 = (const float*)d_in[9];
    const float* c3b1 = (const float*)d_in[10];
    const float* c3w2 = (const float*)d_in[11];
    const float* c3b2 = (const float*)d_in[12];
    const float* mw1  = (const float*)d_in[13];
    const float* mb1  = (const float*)d_in[14];
    const float* mw2  = (const float*)d_in[15];
    const float* mb2  = (const float*)d_in[16];
    const float* mw3  = (const float*)d_in[17];
    const float* mb3  = (const float*)d_in[18];
    const float* mw4  = (const float*)d_in[19];
    const float* mb4  = (const float*)d_in[20];

    void *pX1, *pX2, *pX3;
    cudaGetSymbolAddress(&pX1, g_X1);
    cudaGetSymbolAddress(&pX2, g_X2);
    cudaGetSymbolAddress(&pX3, g_X3);
    float* X1 = (float*)pX1;
    float* X2 = (float*)pX2;
    float* X3 = (float*)pX3;

    // ---- layer 1 (Cin = 1) ----
    sq_kernel  <<<8192, 256>>>(x, 1);
    dist1_kernel<<<dim3(NN, BB), 256>>>(x);
    topk_kernel<<<8192, 256>>>();
    pv_kernel  <<<16384, 256>>>(x, c1w1, c1b1, 1);
    edge_kernel<<<16384, 256>>>(c1w2, c1b2, X1);

    // ---- layer 2 (Cin = 64) ----
    sq_kernel  <<<8192, 256>>>(X1, 64);
    distC_kernel<<<dim3(16, 16, BB), 256>>>(X1);
    topk_kernel<<<8192, 256>>>();
    pv_kernel  <<<16384, 256>>>(X1, c2w1, c2b1, 64);
    edge_kernel<<<16384, 256>>>(c2w2, c2b2, X2);

    // ---- layer 3 (Cin = 64) ----
    sq_kernel  <<<8192, 256>>>(X2, 64);
    distC_kernel<<<dim3(16, 16, BB), 256>>>(X2);
    topk_kernel<<<8192, 256>>>();
    pv_kernel  <<<16384, 256>>>(X2, c3w1, c3b1, 64);
    edge_kernel<<<16384, 256>>>(c3w2, c3b2, X3);

    // ---- head ----
    head_kernel<<<4096, 128>>>(mw1, mb1, mw2, mb2, mw3, mb3, mw4, mb4, (float*)d_out);
}

// round 8
// speedup vs baseline: 1.4166x; 1.4166x over previous
#include <cuda_runtime.h>
#include <cstdint>
#include <math.h>

#define BB   64
#define NN   1024
#define CCH  64
#define KK   16
#define NPTS (BB*NN)

// ---------------- scratch (device globals; no allocation allowed) ----------------
__device__ float g_X1[NPTS*CCH];
__device__ float g_X2[NPTS*CCH];
__device__ float g_X3[NPTS*CCH];
__device__ float g_P [NPTS*CCH];
__device__ float g_V [NPTS*CCH];
__device__ int   g_IDX[NPTS*KK];
__device__ float g_SQ[NPTS];

// monotone float->uint mapping (ascending), valid for negatives too
__device__ __forceinline__ unsigned int f2mono(float d){
    unsigned int u = __float_as_uint(d);
    return (u & 0x80000000u) ? ~u : (u | 0x80000000u);
}

// ---------------- squared norms (C=64 layers) ----------------
__global__ __launch_bounds__(256) void sq_kernel(const float* __restrict__ X){
    int w    = (blockIdx.x*256 + threadIdx.x) >> 5;
    int lane = threadIdx.x & 31;
    if (w >= NPTS) return;
    float s = 0.f;
    for (int k = lane; k < CCH; k += 32){ float v = X[(size_t)w*CCH + k]; s += v*v; }
    #pragma unroll
    for (int off = 16; off; off >>= 1) s += __shfl_down_sync(0xffffffffu, s, off);
    if (lane == 0) g_SQ[w] = s;
}

// ---------------- fused kNN, layer 1 (C = 1) ----------------
// Block = 64 query rows of one batch. xj/sj broadcast from smem, per-thread
// top-16 over a 256-j quarter, then 4-way merge per row.
__global__ __launch_bounds__(256) void knn1_kernel(const float* __restrict__ X){
    __shared__ float xs[NN];
    __shared__ float ss[NN];
    __shared__ unsigned long long cand[64][65];
    int b = blockIdx.y, i0 = blockIdx.x << 6, tid = threadIdx.x;
    const float* Xb = X + (size_t)b*NN;
    for (int t = tid; t < NN; t += 256){ float v = Xb[t]; xs[t] = v; ss[t] = v*v; }
    __syncthreads();

    int srow = tid & 63, q = tid >> 6;
    float xi = xs[i0 + srow];
    float si = ss[i0 + srow];

    unsigned long long keys[16];
    #pragma unroll
    for (int s = 0; s < 16; s++) keys[s] = 0xFFFFFFFFFFFFFFFFull;

    int jb = q << 8;
    #pragma unroll 4
    for (int c = 0; c < 256; c++){
        int j = jb + c;
        float p = __fmul_rn(xi, xs[j]);
        float d = __fmaf_rn(-2.f, p, __fadd_rn(si, ss[j]));   // (si+sj) - 2*dot, ref rounding
        unsigned long long key = ((unsigned long long)f2mono(d) << 32) | (unsigned)j;
        if (key < keys[15]){
            keys[15] = key;
            #pragma unroll
            for (int s = 15; s > 0; --s)
                if (keys[s] < keys[s-1]){ unsigned long long tt = keys[s]; keys[s] = keys[s-1]; keys[s-1] = tt; }
        }
    }
    #pragma unroll
    for (int s = 0; s < 16; s++) cand[srow][(q << 4) + s] = keys[s];
    __syncthreads();

    if (tid < 64){
        int p4[4] = {0,0,0,0};
        size_t ob = ((size_t)(b*NN + i0 + tid))*KK;
        #pragma unroll
        for (int r = 0; r < 16; r++){
            unsigned long long best = 0xFFFFFFFFFFFFFFFFull; int bq = 0;
            #pragma unroll
            for (int q2 = 0; q2 < 4; q2++){
                if (p4[q2] < 16){
                    unsigned long long v = cand[tid][(q2 << 4) + p4[q2]];
                    if (v < best){ best = v; bq = q2; }
                }
            }
            p4[bq]++;
            g_IDX[ob + r] = (int)(best & 0xFFFFFFFFu);
        }
    }
}

// ---------------- fused kNN, C = 64 (layers 2,3) ----------------
// Block = 64 query rows of one batch; loop over 16 j-tiles:
//   GEMM tile (4x4 reg blocking) -> DT smem -> per-thread top-16 update.
// smem union: candidate buffer overlaps AT/BT (dead after the tile loop).
struct KnnSmem {
    union {
        struct { float AT[64][68]; float BT[64][68]; } g;   // 34816 B
        unsigned long long cand[64][65];                    // 33280 B
    };
    float DT[64][65];
};

__global__ __launch_bounds__(256) void knnC_kernel(const float* __restrict__ X){
    __shared__ KnnSmem s;
    int b = blockIdx.y, i0 = blockIdx.x << 6, tid = threadIdx.x;
    const float* Xb = X + ((size_t)b*NN)*CCH;

    for (int t = tid; t < 4096; t += 256){
        int r = t >> 6, k = t & 63;
        s.g.AT[k][r] = Xb[(size_t)(i0 + r)*CCH + k];
        s.g.BT[k][r] = Xb[(size_t)r*CCH + k];
    }
    __syncthreads();

    int er = tid >> 4, cc = tid & 15;
    int srow = tid & 63, q = tid >> 6;
    float si4[4];
    #pragma unroll
    for (int r = 0; r < 4; r++) si4[r] = g_SQ[b*NN + i0 + (er << 2) + r];

    unsigned long long keys[16];
    #pragma unroll
    for (int ss = 0; ss < 16; ss++) keys[ss] = 0xFFFFFFFFFFFFFFFFull;

    for (int jt = 0; jt < 16; jt++){
        // ---- GEMM tile: acc = AT^T * BT ----
        float acc[4][4] = {};
        #pragma unroll 8
        for (int k = 0; k < 64; k++){
            float4 a = *(const float4*)&s.g.AT[k][er << 2];
            float4 w = *(const float4*)&s.g.BT[k][cc << 2];
            acc[0][0]+=a.x*w.x; acc[0][1]+=a.x*w.y; acc[0][2]+=a.x*w.z; acc[0][3]+=a.x*w.w;
            acc[1][0]+=a.y*w.x; acc[1][1]+=a.y*w.y; acc[1][2]+=a.y*w.z; acc[1][3]+=a.y*w.w;
            acc[2][0]+=a.z*w.x; acc[2][1]+=a.z*w.y; acc[2][2]+=a.z*w.z; acc[2][3]+=a.z*w.w;
            acc[3][0]+=a.w*w.x; acc[3][1]+=a.w*w.y; acc[3][2]+=a.w*w.z; acc[3][3]+=a.w*w.w;
        }
        float sj4[4];
        #pragma unroll
        for (int c = 0; c < 4; c++) sj4[c] = g_SQ[b*NN + (jt << 6) + (cc << 2) + c];
        #pragma unroll
        for (int r = 0; r < 4; r++){
            #pragma unroll
            for (int c = 0; c < 4; c++)
                s.DT[(er << 2) + r][(cc << 2) + c] = si4[r] + sj4[c] - 2.f*acc[r][c];
        }
        __syncthreads();

        // ---- prefetch next BT tile (doesn't touch DT) ----
        if (jt < 15){
            int jn = (jt + 1) << 6;
            for (int t = tid; t < 4096; t += 256){
                int r = t >> 6, k = t & 63;
                s.g.BT[k][r] = Xb[(size_t)(jn + r)*CCH + k];
            }
        }

        // ---- top-16 scan of this tile (16 values per thread) ----
        #pragma unroll
        for (int c = 0; c < 16; c++){
            int jl = (q << 4) + c;
            float d = s.DT[srow][jl];
            unsigned long long key = ((unsigned long long)f2mono(d) << 32) | (unsigned)((jt << 6) + jl);
            if (key < keys[15]){
                keys[15] = key;
                #pragma unroll
                for (int ss = 15; ss > 0; --ss)
                    if (keys[ss] < keys[ss-1]){ unsigned long long tt = keys[ss]; keys[ss] = keys[ss-1]; keys[ss-1] = tt; }
            }
        }
        __syncthreads();
    }

    // ---- dump + 4-way merge per row ----
    #pragma unroll
    for (int ss = 0; ss < 16; ss++) s.cand[srow][(q << 4) + ss] = keys[ss];
    __syncthreads();

    if (tid < 64){
        int p4[4] = {0,0,0,0};
        size_t ob = ((size_t)(b*NN + i0 + tid))*KK;
        #pragma unroll
        for (int r = 0; r < 16; r++){
            unsigned long long best = 0xFFFFFFFFFFFFFFFFull; int bq = 0;
            #pragma unroll
            for (int q2 = 0; q2 < 4; q2++){
                if (p4[q2] < 16){
                    unsigned long long v = s.cand[tid][(q2 << 4) + p4[q2]];
                    if (v < best){ best = v; bq = q2; }
                }
            }
            p4[bq]++;
            g_IDX[ob + r] = (int)(best & 0xFFFFFFFFu);
        }
    }
}

// ---------------- per-point transforms: P = x@(W1a-W1b)+b1, V = x@W1b ----------------
__global__ __launch_bounds__(256) void pv_kernel(const float* __restrict__ X,
                                                 const float* __restrict__ W1,
                                                 const float* __restrict__ B1, int Cin){
    __shared__ float xs[4][64];
    int base = blockIdx.x << 2;   // 4 points per block
    for (int t = threadIdx.x; t < 4*Cin; t += 256)
        xs[t/Cin][t%Cin] = X[(size_t)(base + t/Cin)*Cin + (t % Cin)];
    __syncthreads();
    int lp = threadIdx.x >> 6, c = threadIdx.x & 63;
    float p = B1[c], v = 0.f;
    for (int k = 0; k < Cin; k++){
        float xk = xs[lp][k];
        float wa = W1[k*64 + c];
        float wb = W1[(Cin + k)*64 + c];
        v = fmaf(xk, wb, v);
        p = fmaf(xk, wa - wb, p);
    }
    g_P[(size_t)(base + lp)*64 + c] = p;
    g_V[(size_t)(base + lp)*64 + c] = v;
}

// ---------------- edge GEMM + max: out[i][c] = max_j (relu(P_i+V_j) @ W2)[c] + b2[c] ----------------
__global__ __launch_bounds__(256) void edge_kernel(const float* __restrict__ W2,
                                                   const float* __restrict__ B2,
                                                   float* __restrict__ Xout){
    __shared__ __align__(16) float HT [64][68];   // [k][edge]
    __shared__ __align__(16) float W2s[64][68];   // [k][c]
    __shared__ __align__(16) float red[16][68];
    __shared__ int sj[64];
    int tid  = threadIdx.x;
    int base = blockIdx.x << 2;            // 4 points, same batch (1024-aligned batches)
    int b    = base >> 10;
    const float* Vb = g_V + (((size_t)b) << 10)*64;

    if (tid < 64) sj[tid] = g_IDX[(base + (tid >> 4))*KK + (tid & 15)];
    for (int t = tid; t < 4096; t += 256){
        int k = t >> 6, c = t & 63;
        W2s[k][c] = W2[k*64 + c];
    }
    __syncthreads();

    for (int t = tid; t < 4096; t += 256){
        int e = t >> 6, k = t & 63;
        int p = e >> 4;
        float h = g_P[(size_t)(base + p)*64 + k] + Vb[(size_t)sj[e]*64 + k];
        HT[k][e] = fmaxf(h, 0.f);
    }
    __syncthreads();

    int er = tid >> 4, cc = tid & 15;
    float acc[4][4] = {};
    #pragma unroll 8
    for (int k = 0; k < 64; k++){
        float4 h = *(const float4*)&HT [k][er << 2];
        float4 w = *(const float4*)&W2s[k][cc << 2];
        acc[0][0]+=h.x*w.x; acc[0][1]+=h.x*w.y; acc[0][2]+=h.x*w.z; acc[0][3]+=h.x*w.w;
        acc[1][0]+=h.y*w.x; acc[1][1]+=h.y*w.y; acc[1][2]+=h.y*w.z; acc[1][3]+=h.y*w.w;
        acc[2][0]+=h.z*w.x; acc[2][1]+=h.z*w.y; acc[2][2]+=h.z*w.z; acc[2][3]+=h.z*w.w;
        acc[3][0]+=h.w*w.x; acc[3][1]+=h.w*w.y; acc[3][2]+=h.w*w.z; acc[3][3]+=h.w*w.w;
    }
    #pragma unroll
    for (int c = 0; c < 4; c++){
        float m = fmaxf(fmaxf(acc[0][c], acc[1][c]), fmaxf(acc[2][c], acc[3][c]));
        red[er][(cc << 2) + c] = m;
    }
    __syncthreads();
    int p = tid >> 6, c = tid & 63;
    float m = red[4*p][c];
    m = fmaxf(m, red[4*p + 1][c]);
    m = fmaxf(m, red[4*p + 2][c]);
    m = fmaxf(m, red[4*p + 3][c]);
    Xout[(size_t)(base + p)*64 + c] = m + B2[c];
}

// ---------------- MLP head + log_softmax ----------------
__global__ __launch_bounds__(128) void head_kernel(const float* __restrict__ mw1, const float* __restrict__ mb1,
                                                   const float* __restrict__ mw2, const float* __restrict__ mb2,
                                                   const float* __restrict__ mw3, const float* __restrict__ mb3,
                                                   const float* __restrict__ mw4, const float* __restrict__ mb4,
                                                   float* __restrict__ out){
    __shared__ float in[192], h1[128], h2[64], h3[32], o2[2];
    int t = threadIdx.x;
    int p0 = blockIdx.x * 16;
    for (int p = p0; p < p0 + 16; p++){
        if (t < 64){
            in[t      ] = g_X1[(size_t)p*64 + t];
            in[t +  64] = g_X2[(size_t)p*64 + t];
            in[t + 128] = g_X3[(size_t)p*64 + t];
        }
        __syncthreads();
        {
            float a = mb1[t];
            #pragma unroll 8
            for (int k = 0; k < 192; k++) a = fmaf(in[k], mw1[k*128 + t], a);
            h1[t] = fmaxf(a, 0.f);
        }
        __syncthreads();
        if (t < 64){
            float a = mb2[t];
            #pragma unroll 8
            for (int k = 0; k < 128; k++) a = fmaf(h1[k], mw2[k*64 + t], a);
            h2[t] = fmaxf(a, 0.f);
        }
        __syncthreads();
        if (t < 32){
            float a = mb3[t];
            #pragma unroll 8
            for (int k = 0; k < 64; k++) a = fmaf(h2[k], mw3[k*32 + t], a);
            h3[t] = fmaxf(a, 0.f);
        }
        __syncthreads();
        if (t < 2){
            float a = mb4[t];
            #pragma unroll
            for (int k = 0; k < 32; k++) a = fmaf(h3[k], mw4[k*2 + t], a);
            o2[t] = a;
        }
        __syncthreads();
        if (t < 2){
            float m   = fmaxf(o2[0], o2[1]);
            float lse = m + logf(expf(o2[0] - m) + expf(o2[1] - m));
            out[(size_t)p*2 + t] = o2[t] - lse;
        }
        __syncthreads();
    }
}

// ---------------- launch ----------------
extern "C" void kernel_launch(void* const* d_in, const int* in_sizes, int n_in,
                              void* d_out, int out_size){
    const float* x    = (const float*)d_in[0];
    const float* c1w1 = (const float*)d_in[1];
    const float* c1b1 = (const float*)d_in[2];
    const float* c1w2 = (const float*)d_in[3];
    const float* c1b2 = (const float*)d_in[4];
    const float* c2w1 = (const float*)d_in[5];
    const float* c2b1 = (const float*)d_in[6];
    const float* c2w2 = (const float*)d_in[7];
    const float* c2b2 = (const float*)d_in[8];
    const float* c3w1 = (const float*)d_in[9];
    const float* c3b1 = (const float*)d_in[10];
    const float* c3w2 = (const float*)d_in[11];
    const float* c3b2 = (const float*)d_in[12];
    const float* mw1  = (const float*)d_in[13];
    const float* mb1  = (const float*)d_in[14];
    const float* mw2  = (const float*)d_in[15];
    const float* mb2  = (const float*)d_in[16];
    const float* mw3  = (const float*)d_in[17];
    const float* mb3  = (const float*)d_in[18];
    const float* mw4  = (const float*)d_in[19];
    const float* mb4  = (const float*)d_in[20];

    void *pX1, *pX2, *pX3;
    cudaGetSymbolAddress(&pX1, g_X1);
    cudaGetSymbolAddress(&pX2, g_X2);
    cudaGetSymbolAddress(&pX3, g_X3);
    float* X1 = (float*)pX1;
    float* X2 = (float*)pX2;
    float* X3 = (float*)pX3;

    // ---- layer 1 (Cin = 1): fused knn ----
    knn1_kernel<<<dim3(16, BB), 256>>>(x);
    pv_kernel  <<<16384, 256>>>(x, c1w1, c1b1, 1);
    edge_kernel<<<16384, 256>>>(c1w2, c1b2, X1);

    // ---- layer 2 (Cin = 64): fused dist GEMM + knn ----
    sq_kernel  <<<8192, 256>>>(X1);
    knnC_kernel<<<dim3(16, BB), 256>>>(X1);
    pv_kernel  <<<16384, 256>>>(X1, c2w1, c2b1, 64);
    edge_kernel<<<16384, 256>>>(c2w2, c2b2, X2);

    // ---- layer 3 (Cin = 64) ----
    sq_kernel  <<<8192, 256>>>(X2);
    knnC_kernel<<<dim3(16, BB), 256>>>(X2);
    pv_kernel  <<<16384, 256>>>(X2, c3w1, c3b1, 64);
    edge_kernel<<<16384, 256>>>(c3w2, c3b2, X3);

    // ---- head ----
    head_kernel<<<4096, 128>>>(mw1, mb1, mw2, mb2, mw3, mb3, mw4, mb4, (float*)d_out);
}